// round 12
// baseline (speedup 1.0000x reference)
#include <cuda_runtime.h>
#include <cstdint>

// Problem constants
#define NROWS 16384
#define DDIM  2048
#define VDIM  8192

// GEMM tiling (int8): CTA 256x128, K-chunk 128 elements (128B rows), 512 thr
#define BM 256
#define BN 128
#define BKE 128
#define STAGES 3
#define KTILES (DDIM / BKE)          // 16
#define NTILE32 (VDIM / 32)          // 256 candidate tiles of 32 cols
#define QS 18.0f                     // global symmetric int8 scale
#define MARGIN_I 3240.0f             // 10.0 true units * QS*QS

// ---------------------------------------------------------------------------
// Static scratch
// ---------------------------------------------------------------------------
__device__ int8_t g_x8[(size_t)NROWS * DDIM];           // 32 MB x s8 [N][D]
__device__ int8_t g_d8[(size_t)VDIM * DDIM];            // 16 MB di^T s8 [V][D]
__device__ float  g_dTf[(size_t)VDIM * DDIM];           // 64 MB di^T fp32 [V][D]
__device__ float2 g_part[(size_t)NROWS * NTILE32 * 2];  // 67 MB top-2 per (row, 32-tile)

// ---------------------------------------------------------------------------
// Helpers
// ---------------------------------------------------------------------------
__device__ __forceinline__ uint32_t smem_u32(const void* p) {
    uint32_t a;
    asm("{ .reg .u64 t; cvta.to.shared.u64 t, %1; cvt.u32.u64 %0, t; }" : "=r"(a) : "l"(p));
    return a;
}
__device__ __forceinline__ void cpasync16(uint32_t s, const void* g) {
    asm volatile("cp.async.cg.shared.global [%0], [%1], 16;" :: "r"(s), "l"(g));
}
#define CP_COMMIT() asm volatile("cp.async.commit_group;" ::: "memory")

__device__ __forceinline__ void ldsm_x4(uint32_t a, uint32_t& r0, uint32_t& r1,
                                        uint32_t& r2, uint32_t& r3) {
    asm volatile("ldmatrix.sync.aligned.m8n8.x4.shared.b16 {%0,%1,%2,%3}, [%4];"
                 : "=r"(r0), "=r"(r1), "=r"(r2), "=r"(r3) : "r"(a));
}
// int8 IMMA: D(16x8 s32) += A(16x32 s8) * B(32x8 s8, col-major)
__device__ __forceinline__ void mma16832s8(int* d, uint32_t a0, uint32_t a1,
                                           uint32_t a2, uint32_t a3,
                                           uint32_t b0, uint32_t b1) {
    asm volatile(
        "mma.sync.aligned.m16n8k32.row.col.s32.s8.s8.s32 "
        "{%0,%1,%2,%3}, {%4,%5,%6,%7}, {%8,%9}, {%0,%1,%2,%3};"
        : "+r"(d[0]), "+r"(d[1]), "+r"(d[2]), "+r"(d[3])
        : "r"(a0), "r"(a1), "r"(a2), "r"(a3), "r"(b0), "r"(b1));
}

__device__ __forceinline__ int q8(float v) {
    float c = fminf(fmaxf(v * QS, -127.0f), 127.0f);
    return __float2int_rn(c);
}

// ---------------------------------------------------------------------------
// Kernel 1: x fp32 -> s8
// ---------------------------------------------------------------------------
__global__ void k_convert_x(const float* __restrict__ x) {
    const int n4 = NROWS * DDIM / 4;
    for (int j = blockIdx.x * blockDim.x + threadIdx.x; j < n4; j += gridDim.x * blockDim.x) {
        float4 v = reinterpret_cast<const float4*>(x)[j];
        uint32_t b0 = (uint32_t)(q8(v.x) & 0xFF);
        uint32_t b1 = (uint32_t)(q8(v.y) & 0xFF);
        uint32_t b2 = (uint32_t)(q8(v.z) & 0xFF);
        uint32_t b3 = (uint32_t)(q8(v.w) & 0xFF);
        reinterpret_cast<uint32_t*>(g_x8)[j] = b0 | (b1 << 8) | (b2 << 16) | (b3 << 24);
    }
}

// ---------------------------------------------------------------------------
// Kernel 2: transpose di [D,V] -> d8 [V,D] s8 + dTf [V,D] fp32
// ---------------------------------------------------------------------------
__global__ void k_transpose_di(const float* __restrict__ di) {
    __shared__ float t[32][33];
    int v0 = blockIdx.x * 32, d0 = blockIdx.y * 32;
    for (int r = threadIdx.y; r < 32; r += 8)
        t[r][threadIdx.x] = di[(size_t)(d0 + r) * VDIM + v0 + threadIdx.x];
    __syncthreads();
    for (int r = threadIdx.y; r < 32; r += 8) {
        float val = t[threadIdx.x][r];
        size_t o = (size_t)(v0 + r) * DDIM + d0 + threadIdx.x;
        g_dTf[o] = val;
        g_d8[o] = (int8_t)q8(val);
    }
}

// ---------------------------------------------------------------------------
// Kernel 3: int8 IMMA GEMM 256x128 (K-chunk 128B), 3-stage cp.async, 512 thr.
// Warp grid 4(m) x 4(n); warp tile 64x32; epilogue top-2 per 32-col tile.
// ---------------------------------------------------------------------------
#define A_ST (BM * 128)                   // 32 KB
#define B_ST (BN * 128)                   // 16 KB
#define STAGE_BYTES (A_ST + B_ST)         // 48 KB
#define GEMM_SMEM (STAGES * STAGE_BYTES)  // 144 KB

__device__ __forceinline__ void load_stage(uint32_t sb, int s, int kt,
                                           int m0, int v0, int tid) {
    uint32_t ab = sb + s * STAGE_BYTES;
    uint32_t bb = ab + A_ST;
    int k0 = kt * BKE;
    #pragma unroll
    for (int i = 0; i < 4; i++) {   // A: 256 rows x 8 x 16B = 2048 chunks
        int idx = tid + i * 512;
        int r = idx >> 3, c = idx & 7;
        cpasync16(ab + r * 128 + ((c ^ (r & 7)) << 4),
                  &g_x8[(size_t)(m0 + r) * DDIM + k0 + c * 16]);
    }
    #pragma unroll
    for (int i = 0; i < 2; i++) {   // B: 128 rows x 8 x 16B = 1024 chunks
        int idx = tid + i * 512;
        int r = idx >> 3, c = idx & 7;
        cpasync16(bb + r * 128 + ((c ^ (r & 7)) << 4),
                  &g_d8[(size_t)(v0 + r) * DDIM + k0 + c * 16]);
    }
    CP_COMMIT();
}

// merge top-2 pairs
__device__ __forceinline__ void top2_merge(float& b, float& s, int& bi, int& si,
                                           float b2, float s2, int bi2, int si2) {
    if (b2 > b) {
        float nb = b2; int nbi = bi2;
        float ns = fmaxf(b, s2); int nsi = (b >= s2) ? bi : si2;
        b = nb; bi = nbi; s = ns; si = nsi;
    } else {
        if (b2 > s) { s = b2; si = bi2; }
        else if (s2 > s) { s = s2; si = si2; }
    }
}

__global__ void __launch_bounds__(512, 1) k_gemm() {
    extern __shared__ char smem[];
    uint32_t sb = smem_u32(smem);
    int tid = threadIdx.x, wid = tid >> 5, lane = tid & 31;
    int wm = wid >> 2;         // 0..3
    int wn = wid & 3;          // 0..3
    int m0 = blockIdx.y * BM;
    int v0 = blockIdx.x * BN;

    int acc[4][4][4];          // [mf][nf][reg] s32
    #pragma unroll
    for (int a = 0; a < 4; a++)
        #pragma unroll
        for (int b = 0; b < 4; b++)
            #pragma unroll
            for (int c = 0; c < 4; c++) acc[a][b][c] = 0;

    load_stage(sb, 0, 0, m0, v0, tid);
    load_stage(sb, 1, 1, m0, v0, tid);

    int mi = lane >> 3;        // ldmatrix matrix index 0..3
    int rin = lane & 7;        // row within 8x8 matrix

    for (int i = 0; i < KTILES; i++) {
        if (i + 1 < KTILES) {
            asm volatile("cp.async.wait_group 1;" ::: "memory");
        } else {
            asm volatile("cp.async.wait_group 0;" ::: "memory");
        }
        __syncthreads();

        if (i + 2 < KTILES) load_stage(sb, (i + 2) % STAGES, i + 2, m0, v0, tid);

        uint32_t ab = sb + (i % STAGES) * STAGE_BYTES;
        uint32_t bb = ab + A_ST;

        #pragma unroll
        for (int ks = 0; ks < 4; ks++) {   // 4 x k32 within the 128B chunk
            // A frags: x4 = (r0-7,klo16B),(r8-15,klo),(r0-7,khi),(r8-15,khi)
            uint32_t af[4][4];
            #pragma unroll
            for (int mf = 0; mf < 4; mf++) {
                int row = wm * 64 + mf * 16 + (mi & 1) * 8 + rin;
                int kc = ks * 2 + (mi >> 1);
                ldsm_x4(ab + row * 128 + ((kc ^ (row & 7)) << 4),
                        af[mf][0], af[mf][1], af[mf][2], af[mf][3]);
            }
            // B frags: x4 = (n0-7,klo),(n0-7,khi),(n8-15,klo),(n8-15,khi)
            uint32_t bfr[2][4];
            #pragma unroll
            for (int nf2 = 0; nf2 < 2; nf2++) {
                int nrow = wn * 32 + (nf2 * 2 + (mi >> 1)) * 8 + rin;
                int kc = ks * 2 + (mi & 1);
                ldsm_x4(bb + nrow * 128 + ((kc ^ (nrow & 7)) << 4),
                        bfr[nf2][0], bfr[nf2][1], bfr[nf2][2], bfr[nf2][3]);
            }
            #pragma unroll
            for (int mf = 0; mf < 4; mf++)
                #pragma unroll
                for (int nf = 0; nf < 4; nf++) {
                    uint32_t b0 = bfr[nf >> 1][(nf & 1) * 2 + 0];
                    uint32_t b1 = bfr[nf >> 1][(nf & 1) * 2 + 1];
                    mma16832s8(acc[mf][nf], af[mf][0], af[mf][1], af[mf][2], af[mf][3],
                               b0, b1);
                }
        }
        __syncthreads();
    }

    // Epilogue: per-row top-2 over this warp's 32 columns (one 32-tile per warp).
    int tileN = blockIdx.x * 4 + wn;
    int colbase = v0 + wn * 32 + (lane & 3) * 2;
    #pragma unroll
    for (int mf = 0; mf < 4; mf++) {
        float bA = -3.4e38f, sA = -3.4e38f, bB = -3.4e38f, sB = -3.4e38f;
        int biA = 0, siA = 0, biB = 0, siB = 0;
        #pragma unroll
        for (int nf = 0; nf < 4; nf++) {
            #pragma unroll
            for (int e = 0; e < 2; e++) {
                int col = colbase + nf * 8 + e;
                top2_merge(bA, sA, biA, siA, (float)acc[mf][nf][e], -3.4e38f, col, 0);
                top2_merge(bB, sB, biB, siB, (float)acc[mf][nf][2 + e], -3.4e38f, col, 0);
            }
        }
        #pragma unroll
        for (int o = 1; o <= 2; o <<= 1) {
            float b2 = __shfl_xor_sync(0xFFFFFFFFu, bA, o);
            float s2 = __shfl_xor_sync(0xFFFFFFFFu, sA, o);
            int bi2 = __shfl_xor_sync(0xFFFFFFFFu, biA, o);
            int si2 = __shfl_xor_sync(0xFFFFFFFFu, siA, o);
            top2_merge(bA, sA, biA, siA, b2, s2, bi2, si2);
            b2 = __shfl_xor_sync(0xFFFFFFFFu, bB, o);
            s2 = __shfl_xor_sync(0xFFFFFFFFu, sB, o);
            bi2 = __shfl_xor_sync(0xFFFFFFFFu, biB, o);
            si2 = __shfl_xor_sync(0xFFFFFFFFu, siB, o);
            top2_merge(bB, sB, biB, siB, b2, s2, bi2, si2);
        }
        if ((lane & 3) == 0) {
            int rowA = m0 + wm * 64 + mf * 16 + (lane >> 2);
            float2* pA = &g_part[((size_t)rowA * NTILE32 + tileN) * 2];
            pA[0] = make_float2(bA, __int_as_float(biA));
            pA[1] = make_float2(sA, __int_as_float(siA));
            float2* pB = &g_part[((size_t)(rowA + 8) * NTILE32 + tileN) * 2];
            pB[0] = make_float2(bB, __int_as_float(biB));
            pB[1] = make_float2(sB, __int_as_float(siB));
        }
    }
}

// ---------------------------------------------------------------------------
// Kernel 4: refine. One warp per row over 256 tiles (float4 = one tile's top-2).
// ---------------------------------------------------------------------------
__global__ void __launch_bounds__(256) k_refine(const float* __restrict__ x,
                                               float* __restrict__ out) {
    int gwarp = (blockIdx.x * blockDim.x + threadIdx.x) >> 5;
    int lid = threadIdx.x & 31;
    if (gwarp >= NROWS) return;
    int row = gwarp;

    const float4* p4 = reinterpret_cast<const float4*>(&g_part[(size_t)row * NTILE32 * 2]);

    // pass 1: max of stored (quantized-domain) best scores
    float mx = -3.4e38f;
    float4 qv[8];
    #pragma unroll
    for (int g = 0; g < 8; g++) {
        qv[g] = p4[g * 32 + lid];          // (best, bi, sec, si)
        mx = fmaxf(mx, qv[g].x);
    }
    #pragma unroll
    for (int o = 16; o; o >>= 1) mx = fmaxf(mx, __shfl_xor_sync(0xFFFFFFFFu, mx, o));
    float thr = mx - MARGIN_I;

    const float* xr = x + (size_t)row * DDIM;
    float bestv = -3.4e38f;
    int besti = 0x7FFFFFFF;

    // pass 2: exact fp32 dot for every candidate above threshold (best + sec)
    #pragma unroll
    for (int g = 0; g < 8; g++) {
        #pragma unroll
        for (int h = 0; h < 2; h++) {
            float sc = h ? qv[g].z : qv[g].x;
            int myidx = __float_as_int(h ? qv[g].w : qv[g].y);
            unsigned mask = __ballot_sync(0xFFFFFFFFu, sc >= thr);
            while (mask) {
                int s = __ffs(mask) - 1;
                mask &= mask - 1;
                int idx = __shfl_sync(0xFFFFFFFFu, myidx, s);
                const float* dr = g_dTf + (size_t)idx * DDIM;
                float a = 0.0f;
                #pragma unroll 8
                for (int k = lid; k < DDIM; k += 32) a = fmaf(xr[k], dr[k], a);
                #pragma unroll
                for (int o = 16; o; o >>= 1) a += __shfl_xor_sync(0xFFFFFFFFu, a, o);
                if (a > bestv || (a == bestv && idx < besti)) { bestv = a; besti = idx; }
            }
        }
    }
    if (lid == 0) out[row] = (float)besti;
}

// ---------------------------------------------------------------------------
// Launch
// ---------------------------------------------------------------------------
extern "C" void kernel_launch(void* const* d_in, const int* in_sizes, int n_in,
                              void* d_out, int out_size) {
    const float* x = (const float*)d_in[0];
    const float* di = (const float*)d_in[1];
    float* out = (float*)d_out;

    cudaFuncSetAttribute(k_gemm, cudaFuncAttributeMaxDynamicSharedMemorySize, GEMM_SMEM);

    k_convert_x<<<2048, 256>>>(x);

    dim3 tg(VDIM / 32, DDIM / 32);
    k_transpose_di<<<tg, dim3(32, 8)>>>(di);

    dim3 gg(VDIM / BN, NROWS / BM);  // 64 x 64 = 4096 CTAs
    k_gemm<<<gg, 512, GEMM_SMEM>>>();

    k_refine<<<NROWS / 8, 256>>>(x, out);
}

// round 13
// speedup vs baseline: 1.1506x; 1.1506x over previous
#include <cuda_runtime.h>
#include <cstdint>

// Problem constants
#define NROWS 16384
#define DDIM  2048
#define VDIM  8192

// GEMM tiling (int8): CTA 128x128, K-chunk 128 elements (128B rows)
#define BM 128
#define BN 128
#define BKE 128
#define STAGES 3
#define KTILES (DDIM / BKE)          // 16
#define NTILE32 (VDIM / 32)          // 256 candidate tiles of 32 cols
#define QS 18.0f                     // global symmetric int8 scale
#define MARGIN_I 3240.0f             // 10.0 true units * QS*QS

// ---------------------------------------------------------------------------
// Static scratch
// ---------------------------------------------------------------------------
__device__ int8_t g_x8[(size_t)NROWS * DDIM];           // 32 MB x s8 [N][D]
__device__ int8_t g_d8[(size_t)VDIM * DDIM];            // 16 MB di^T s8 [V][D]
__device__ float  g_dTf[(size_t)VDIM * DDIM];           // 64 MB di^T fp32 [V][D]
__device__ float2 g_part[(size_t)NROWS * NTILE32 * 2];  // 67 MB top-2 per (row, 32-tile)

// ---------------------------------------------------------------------------
// Helpers
// ---------------------------------------------------------------------------
__device__ __forceinline__ uint32_t smem_u32(const void* p) {
    uint32_t a;
    asm("{ .reg .u64 t; cvta.to.shared.u64 t, %1; cvt.u32.u64 %0, t; }" : "=r"(a) : "l"(p));
    return a;
}
__device__ __forceinline__ void cpasync16(uint32_t s, const void* g) {
    asm volatile("cp.async.cg.shared.global [%0], [%1], 16;" :: "r"(s), "l"(g));
}
#define CP_COMMIT() asm volatile("cp.async.commit_group;" ::: "memory")

__device__ __forceinline__ void ldsm_x4(uint32_t a, uint32_t& r0, uint32_t& r1,
                                        uint32_t& r2, uint32_t& r3) {
    asm volatile("ldmatrix.sync.aligned.m8n8.x4.shared.b16 {%0,%1,%2,%3}, [%4];"
                 : "=r"(r0), "=r"(r1), "=r"(r2), "=r"(r3) : "r"(a));
}
// int8 IMMA: D(16x8 s32) += A(16x32 s8) * B(32x8 s8, col-major)
__device__ __forceinline__ void mma16832s8(int* d, uint32_t a0, uint32_t a1,
                                           uint32_t a2, uint32_t a3,
                                           uint32_t b0, uint32_t b1) {
    asm volatile(
        "mma.sync.aligned.m16n8k32.row.col.s32.s8.s8.s32 "
        "{%0,%1,%2,%3}, {%4,%5,%6,%7}, {%8,%9}, {%0,%1,%2,%3};"
        : "+r"(d[0]), "+r"(d[1]), "+r"(d[2]), "+r"(d[3])
        : "r"(a0), "r"(a1), "r"(a2), "r"(a3), "r"(b0), "r"(b1));
}

__device__ __forceinline__ int q8(float v) {
    float c = fminf(fmaxf(v * QS, -127.0f), 127.0f);
    return __float2int_rn(c);
}

// ---------------------------------------------------------------------------
// Kernel 1: x fp32 -> s8
// ---------------------------------------------------------------------------
__global__ void k_convert_x(const float* __restrict__ x) {
    const int n4 = NROWS * DDIM / 4;
    for (int j = blockIdx.x * blockDim.x + threadIdx.x; j < n4; j += gridDim.x * blockDim.x) {
        float4 v = reinterpret_cast<const float4*>(x)[j];
        uint32_t b0 = (uint32_t)(q8(v.x) & 0xFF);
        uint32_t b1 = (uint32_t)(q8(v.y) & 0xFF);
        uint32_t b2 = (uint32_t)(q8(v.z) & 0xFF);
        uint32_t b3 = (uint32_t)(q8(v.w) & 0xFF);
        reinterpret_cast<uint32_t*>(g_x8)[j] = b0 | (b1 << 8) | (b2 << 16) | (b3 << 24);
    }
}

// ---------------------------------------------------------------------------
// Kernel 2: transpose di [D,V] -> d8 [V,D] s8 + dTf [V,D] fp32
// ---------------------------------------------------------------------------
__global__ void k_transpose_di(const float* __restrict__ di) {
    __shared__ float t[32][33];
    int v0 = blockIdx.x * 32, d0 = blockIdx.y * 32;
    for (int r = threadIdx.y; r < 32; r += 8)
        t[r][threadIdx.x] = di[(size_t)(d0 + r) * VDIM + v0 + threadIdx.x];
    __syncthreads();
    for (int r = threadIdx.y; r < 32; r += 8) {
        float val = t[threadIdx.x][r];
        size_t o = (size_t)(v0 + r) * DDIM + d0 + threadIdx.x;
        g_dTf[o] = val;
        g_d8[o] = (int8_t)q8(val);
    }
}

// ---------------------------------------------------------------------------
// Kernel 3: int8 IMMA GEMM 128x128 (K-chunk 128B), 3-stage cp.async.
// Warp grid 2(m) x 4(n); warp tile 64x32; epilogue top-2 per 32-col tile.
// Single barrier per iteration (top-of-loop) — end barrier proven redundant.
// ---------------------------------------------------------------------------
#define A_ST (BM * 128)                   // 16 KB
#define B_ST (BN * 128)                   // 16 KB
#define STAGE_BYTES (A_ST + B_ST)         // 32 KB
#define GEMM_SMEM (STAGES * STAGE_BYTES)  // 96 KB

__device__ __forceinline__ void load_stage(uint32_t sb, int s, int kt,
                                           int m0, int v0, int tid) {
    uint32_t ab = sb + s * STAGE_BYTES;
    uint32_t bb = ab + A_ST;
    int k0 = kt * BKE;
    #pragma unroll
    for (int i = 0; i < 4; i++) {   // A: 128 rows x 8 x 16B
        int idx = tid + i * 256;
        int r = idx >> 3, c = idx & 7;
        cpasync16(ab + r * 128 + ((c ^ (r & 7)) << 4),
                  &g_x8[(size_t)(m0 + r) * DDIM + k0 + c * 16]);
    }
    #pragma unroll
    for (int i = 0; i < 4; i++) {   // B: 128 rows x 8 x 16B
        int idx = tid + i * 256;
        int r = idx >> 3, c = idx & 7;
        cpasync16(bb + r * 128 + ((c ^ (r & 7)) << 4),
                  &g_d8[(size_t)(v0 + r) * DDIM + k0 + c * 16]);
    }
    CP_COMMIT();
}

// merge top-2 pairs
__device__ __forceinline__ void top2_merge(float& b, float& s, int& bi, int& si,
                                           float b2, float s2, int bi2, int si2) {
    if (b2 > b) {
        float nb = b2; int nbi = bi2;
        float ns = fmaxf(b, s2); int nsi = (b >= s2) ? bi : si2;
        b = nb; bi = nbi; s = ns; si = nsi;
    } else {
        if (b2 > s) { s = b2; si = bi2; }
        else if (s2 > s) { s = s2; si = si2; }
    }
}

__global__ void __launch_bounds__(256, 2) k_gemm() {
    extern __shared__ char smem[];
    uint32_t sb = smem_u32(smem);
    int tid = threadIdx.x, wid = tid >> 5, lane = tid & 31;
    int wm = wid >> 2;         // 0..1
    int wn = wid & 3;          // 0..3
    int m0 = blockIdx.y * BM;
    int v0 = blockIdx.x * BN;

    int acc[4][4][4];          // [mf][nf][reg] s32
    #pragma unroll
    for (int a = 0; a < 4; a++)
        #pragma unroll
        for (int b = 0; b < 4; b++)
            #pragma unroll
            for (int c = 0; c < 4; c++) acc[a][b][c] = 0;

    load_stage(sb, 0, 0, m0, v0, tid);
    load_stage(sb, 1, 1, m0, v0, tid);

    int mi = lane >> 3;        // ldmatrix matrix index 0..3
    int rin = lane & 7;        // row within 8x8 matrix

    for (int i = 0; i < KTILES; i++) {
        if (i + 1 < KTILES) {
            asm volatile("cp.async.wait_group 1;" ::: "memory");
        } else {
            asm volatile("cp.async.wait_group 0;" ::: "memory");
        }
        // Single barrier: arriving here implies all warps finished iter i-1's
        // reads, so overwriting stage (i+2)%3 below is safe.
        __syncthreads();

        if (i + 2 < KTILES) load_stage(sb, (i + 2) % STAGES, i + 2, m0, v0, tid);

        uint32_t ab = sb + (i % STAGES) * STAGE_BYTES;
        uint32_t bb = ab + A_ST;

        #pragma unroll
        for (int ks = 0; ks < 4; ks++) {   // 4 x k32 within the 128B chunk
            uint32_t af[4][4];
            #pragma unroll
            for (int mf = 0; mf < 4; mf++) {
                int row = wm * 64 + mf * 16 + (mi & 1) * 8 + rin;
                int kc = ks * 2 + (mi >> 1);
                ldsm_x4(ab + row * 128 + ((kc ^ (row & 7)) << 4),
                        af[mf][0], af[mf][1], af[mf][2], af[mf][3]);
            }
            uint32_t bfr[2][4];
            #pragma unroll
            for (int nf2 = 0; nf2 < 2; nf2++) {
                int nrow = wn * 32 + (nf2 * 2 + (mi >> 1)) * 8 + rin;
                int kc = ks * 2 + (mi & 1);
                ldsm_x4(bb + nrow * 128 + ((kc ^ (nrow & 7)) << 4),
                        bfr[nf2][0], bfr[nf2][1], bfr[nf2][2], bfr[nf2][3]);
            }
            #pragma unroll
            for (int mf = 0; mf < 4; mf++)
                #pragma unroll
                for (int nf = 0; nf < 4; nf++) {
                    uint32_t b0 = bfr[nf >> 1][(nf & 1) * 2 + 0];
                    uint32_t b1 = bfr[nf >> 1][(nf & 1) * 2 + 1];
                    mma16832s8(acc[mf][nf], af[mf][0], af[mf][1], af[mf][2], af[mf][3],
                               b0, b1);
                }
        }
        // no end-of-iteration barrier (redundant; see comment above)
    }

    // Epilogue: per-row top-2 over this warp's 32 columns (one 32-tile per warp).
    int tileN = blockIdx.x * 4 + wn;
    int colbase = v0 + wn * 32 + (lane & 3) * 2;
    #pragma unroll
    for (int mf = 0; mf < 4; mf++) {
        float bA = -3.4e38f, sA = -3.4e38f, bB = -3.4e38f, sB = -3.4e38f;
        int biA = 0, siA = 0, biB = 0, siB = 0;
        #pragma unroll
        for (int nf = 0; nf < 4; nf++) {
            #pragma unroll
            for (int e = 0; e < 2; e++) {
                int col = colbase + nf * 8 + e;
                top2_merge(bA, sA, biA, siA, (float)acc[mf][nf][e], -3.4e38f, col, 0);
                top2_merge(bB, sB, biB, siB, (float)acc[mf][nf][2 + e], -3.4e38f, col, 0);
            }
        }
        #pragma unroll
        for (int o = 1; o <= 2; o <<= 1) {
            float b2 = __shfl_xor_sync(0xFFFFFFFFu, bA, o);
            float s2 = __shfl_xor_sync(0xFFFFFFFFu, sA, o);
            int bi2 = __shfl_xor_sync(0xFFFFFFFFu, biA, o);
            int si2 = __shfl_xor_sync(0xFFFFFFFFu, siA, o);
            top2_merge(bA, sA, biA, siA, b2, s2, bi2, si2);
            b2 = __shfl_xor_sync(0xFFFFFFFFu, bB, o);
            s2 = __shfl_xor_sync(0xFFFFFFFFu, sB, o);
            bi2 = __shfl_xor_sync(0xFFFFFFFFu, biB, o);
            si2 = __shfl_xor_sync(0xFFFFFFFFu, siB, o);
            top2_merge(bB, sB, biB, siB, b2, s2, bi2, si2);
        }
        if ((lane & 3) == 0) {
            int rowA = m0 + wm * 64 + mf * 16 + (lane >> 2);
            float2* pA = &g_part[((size_t)rowA * NTILE32 + tileN) * 2];
            pA[0] = make_float2(bA, __int_as_float(biA));
            pA[1] = make_float2(sA, __int_as_float(siA));
            float2* pB = &g_part[((size_t)(rowA + 8) * NTILE32 + tileN) * 2];
            pB[0] = make_float2(bB, __int_as_float(biB));
            pB[1] = make_float2(sB, __int_as_float(siB));
        }
    }
}

// ---------------------------------------------------------------------------
// Kernel 4: refine. One warp per row; float4-vectorized exact fp32 dots.
// ---------------------------------------------------------------------------
__global__ void __launch_bounds__(256) k_refine(const float* __restrict__ x,
                                               float* __restrict__ out) {
    int gwarp = (blockIdx.x * blockDim.x + threadIdx.x) >> 5;
    int lid = threadIdx.x & 31;
    if (gwarp >= NROWS) return;
    int row = gwarp;

    const float4* p4 = reinterpret_cast<const float4*>(&g_part[(size_t)row * NTILE32 * 2]);

    // pass 1: max of stored (quantized-domain) best scores
    float mx = -3.4e38f;
    float4 qv[8];
    #pragma unroll
    for (int g = 0; g < 8; g++) {
        qv[g] = p4[g * 32 + lid];          // (best, bi, sec, si)
        mx = fmaxf(mx, qv[g].x);
    }
    #pragma unroll
    for (int o = 16; o; o >>= 1) mx = fmaxf(mx, __shfl_xor_sync(0xFFFFFFFFu, mx, o));
    float thr = mx - MARGIN_I;

    const float4* xr4 = reinterpret_cast<const float4*>(x + (size_t)row * DDIM);
    float bestv = -3.4e38f;
    int besti = 0x7FFFFFFF;

    // pass 2: exact fp32 dot for every candidate above threshold (best + sec)
    #pragma unroll
    for (int g = 0; g < 8; g++) {
        #pragma unroll
        for (int h = 0; h < 2; h++) {
            float sc = h ? qv[g].z : qv[g].x;
            int myidx = __float_as_int(h ? qv[g].w : qv[g].y);
            unsigned mask = __ballot_sync(0xFFFFFFFFu, sc >= thr);
            while (mask) {
                int s = __ffs(mask) - 1;
                mask &= mask - 1;
                int idx = __shfl_sync(0xFFFFFFFFu, myidx, s);
                const float4* dr4 = reinterpret_cast<const float4*>(
                    g_dTf + (size_t)idx * DDIM);
                float a = 0.0f;
                #pragma unroll 4
                for (int k = lid; k < DDIM / 4; k += 32) {
                    float4 xv = xr4[k], dv = dr4[k];
                    a = fmaf(xv.x, dv.x, a);
                    a = fmaf(xv.y, dv.y, a);
                    a = fmaf(xv.z, dv.z, a);
                    a = fmaf(xv.w, dv.w, a);
                }
                #pragma unroll
                for (int o = 16; o; o >>= 1) a += __shfl_xor_sync(0xFFFFFFFFu, a, o);
                if (a > bestv || (a == bestv && idx < besti)) { bestv = a; besti = idx; }
            }
        }
    }
    if (lid == 0) out[row] = (float)besti;
}

// ---------------------------------------------------------------------------
// Launch
// ---------------------------------------------------------------------------
extern "C" void kernel_launch(void* const* d_in, const int* in_sizes, int n_in,
                              void* d_out, int out_size) {
    const float* x = (const float*)d_in[0];
    const float* di = (const float*)d_in[1];
    float* out = (float*)d_out;

    cudaFuncSetAttribute(k_gemm, cudaFuncAttributeMaxDynamicSharedMemorySize, GEMM_SMEM);

    k_convert_x<<<2048, 256>>>(x);

    dim3 tg(VDIM / 32, DDIM / 32);
    k_transpose_di<<<tg, dim3(32, 8)>>>(di);

    dim3 gg(VDIM / BN, NROWS / BM);  // 64 x 128 = 8192 CTAs
    k_gemm<<<gg, 256, GEMM_SMEM>>>();

    k_refine<<<NROWS / 8, 256>>>(x, out);
}

// round 14
// speedup vs baseline: 1.2010x; 1.0438x over previous
#include <cuda_runtime.h>
#include <cstdint>

// Problem constants
#define NROWS 16384
#define DDIM  2048
#define VDIM  8192

// GEMM tiling (int8): CTA 128x128, K-chunk 128 elements (128B rows)
#define BM 128
#define BN 128
#define BKE 128
#define STAGES 3
#define KTILES (DDIM / BKE)          // 16
#define NTILE32 (VDIM / 32)          // 256 candidate tiles of 32 cols
#define QS 18.0f                     // global symmetric int8 scale
#define MARGIN_I 3240.0f             // 10.0 true units * QS*QS

// ---------------------------------------------------------------------------
// Static scratch
// ---------------------------------------------------------------------------
__device__ int8_t g_x8[(size_t)NROWS * DDIM];           // 32 MB x s8 [N][D]
__device__ int8_t g_d8[(size_t)VDIM * DDIM];            // 16 MB di^T s8 [V][D]
__device__ float  g_dTf[(size_t)VDIM * DDIM];           // 64 MB di^T fp32 [V][D]
__device__ float2 g_part[(size_t)NROWS * NTILE32 * 2];  // 67 MB top-2 per (row, 32-tile)

// ---------------------------------------------------------------------------
// Helpers
// ---------------------------------------------------------------------------
__device__ __forceinline__ uint32_t smem_u32(const void* p) {
    uint32_t a;
    asm("{ .reg .u64 t; cvta.to.shared.u64 t, %1; cvt.u32.u64 %0, t; }" : "=r"(a) : "l"(p));
    return a;
}
__device__ __forceinline__ void cpasync16(uint32_t s, const void* g) {
    asm volatile("cp.async.cg.shared.global [%0], [%1], 16;" :: "r"(s), "l"(g));
}
#define CP_COMMIT() asm volatile("cp.async.commit_group;" ::: "memory")

__device__ __forceinline__ void ldsm_x4(uint32_t a, uint32_t& r0, uint32_t& r1,
                                        uint32_t& r2, uint32_t& r3) {
    asm volatile("ldmatrix.sync.aligned.m8n8.x4.shared.b16 {%0,%1,%2,%3}, [%4];"
                 : "=r"(r0), "=r"(r1), "=r"(r2), "=r"(r3) : "r"(a));
}
// int8 IMMA: D(16x8 s32) += A(16x32 s8) * B(32x8 s8, col-major)
__device__ __forceinline__ void mma16832s8(int* d, uint32_t a0, uint32_t a1,
                                           uint32_t a2, uint32_t a3,
                                           uint32_t b0, uint32_t b1) {
    asm volatile(
        "mma.sync.aligned.m16n8k32.row.col.s32.s8.s8.s32 "
        "{%0,%1,%2,%3}, {%4,%5,%6,%7}, {%8,%9}, {%0,%1,%2,%3};"
        : "+r"(d[0]), "+r"(d[1]), "+r"(d[2]), "+r"(d[3])
        : "r"(a0), "r"(a1), "r"(a2), "r"(a3), "r"(b0), "r"(b1));
}

__device__ __forceinline__ int q8(float v) {
    float c = fminf(fmaxf(v * QS, -127.0f), 127.0f);
    return __float2int_rn(c);
}

// ---------------------------------------------------------------------------
// Kernel 1: x fp32 -> s8
// ---------------------------------------------------------------------------
__global__ void k_convert_x(const float* __restrict__ x) {
    const int n4 = NROWS * DDIM / 4;
    for (int j = blockIdx.x * blockDim.x + threadIdx.x; j < n4; j += gridDim.x * blockDim.x) {
        float4 v = reinterpret_cast<const float4*>(x)[j];
        uint32_t b0 = (uint32_t)(q8(v.x) & 0xFF);
        uint32_t b1 = (uint32_t)(q8(v.y) & 0xFF);
        uint32_t b2 = (uint32_t)(q8(v.z) & 0xFF);
        uint32_t b3 = (uint32_t)(q8(v.w) & 0xFF);
        reinterpret_cast<uint32_t*>(g_x8)[j] = b0 | (b1 << 8) | (b2 << 16) | (b3 << 24);
    }
}

// ---------------------------------------------------------------------------
// Kernel 2: transpose di [D,V] -> d8 [V,D] s8 + dTf [V,D] fp32
// ---------------------------------------------------------------------------
__global__ void k_transpose_di(const float* __restrict__ di) {
    __shared__ float t[32][33];
    int v0 = blockIdx.x * 32, d0 = blockIdx.y * 32;
    for (int r = threadIdx.y; r < 32; r += 8)
        t[r][threadIdx.x] = di[(size_t)(d0 + r) * VDIM + v0 + threadIdx.x];
    __syncthreads();
    for (int r = threadIdx.y; r < 32; r += 8) {
        float val = t[threadIdx.x][r];
        size_t o = (size_t)(v0 + r) * DDIM + d0 + threadIdx.x;
        g_dTf[o] = val;
        g_d8[o] = (int8_t)q8(val);
    }
}

// ---------------------------------------------------------------------------
// Kernel 3: int8 IMMA GEMM 128x128 (K-chunk 128B), 3-stage cp.async.
// Warp grid 2(m) x 4(n); warp tile 64x32; epilogue top-2 per 32-col tile.
// Single barrier per iteration; K-loop unrolled by 3 (stage period).
// ---------------------------------------------------------------------------
#define A_ST (BM * 128)                   // 16 KB
#define B_ST (BN * 128)                   // 16 KB
#define STAGE_BYTES (A_ST + B_ST)         // 32 KB
#define GEMM_SMEM (STAGES * STAGE_BYTES)  // 96 KB

__device__ __forceinline__ void load_stage(uint32_t sb, int s, int kt,
                                           int m0, int v0, int tid) {
    uint32_t ab = sb + s * STAGE_BYTES;
    uint32_t bb = ab + A_ST;
    int k0 = kt * BKE;
    #pragma unroll
    for (int i = 0; i < 4; i++) {   // A: 128 rows x 8 x 16B
        int idx = tid + i * 256;
        int r = idx >> 3, c = idx & 7;
        cpasync16(ab + r * 128 + ((c ^ (r & 7)) << 4),
                  &g_x8[(size_t)(m0 + r) * DDIM + k0 + c * 16]);
    }
    #pragma unroll
    for (int i = 0; i < 4; i++) {   // B: 128 rows x 8 x 16B
        int idx = tid + i * 256;
        int r = idx >> 3, c = idx & 7;
        cpasync16(bb + r * 128 + ((c ^ (r & 7)) << 4),
                  &g_d8[(size_t)(v0 + r) * DDIM + k0 + c * 16]);
    }
    CP_COMMIT();
}

// merge top-2 pairs
__device__ __forceinline__ void top2_merge(float& b, float& s, int& bi, int& si,
                                           float b2, float s2, int bi2, int si2) {
    if (b2 > b) {
        float nb = b2; int nbi = bi2;
        float ns = fmaxf(b, s2); int nsi = (b >= s2) ? bi : si2;
        b = nb; bi = nbi; s = ns; si = nsi;
    } else {
        if (b2 > s) { s = b2; si = bi2; }
        else if (s2 > s) { s = s2; si = si2; }
    }
}

__global__ void __launch_bounds__(256, 2) k_gemm() {
    extern __shared__ char smem[];
    uint32_t sb = smem_u32(smem);
    int tid = threadIdx.x, wid = tid >> 5, lane = tid & 31;
    int wm = wid >> 2;         // 0..1
    int wn = wid & 3;          // 0..3
    int m0 = blockIdx.y * BM;
    int v0 = blockIdx.x * BN;

    int acc[4][4][4];          // [mf][nf][reg] s32
    #pragma unroll
    for (int a = 0; a < 4; a++)
        #pragma unroll
        for (int b = 0; b < 4; b++)
            #pragma unroll
            for (int c = 0; c < 4; c++) acc[a][b][c] = 0;

    load_stage(sb, 0, 0, m0, v0, tid);
    load_stage(sb, 1, 1, m0, v0, tid);

    int mi = lane >> 3;        // ldmatrix matrix index 0..3
    int rin = lane & 7;        // row within 8x8 matrix

    #pragma unroll 3
    for (int i = 0; i < KTILES; i++) {
        if (i + 1 < KTILES) {
            asm volatile("cp.async.wait_group 1;" ::: "memory");
        } else {
            asm volatile("cp.async.wait_group 0;" ::: "memory");
        }
        // Single barrier: arriving here implies all warps finished iter i-1's
        // reads, so overwriting stage (i+2)%3 below is safe.
        __syncthreads();

        if (i + 2 < KTILES) load_stage(sb, (i + 2) % STAGES, i + 2, m0, v0, tid);

        uint32_t ab = sb + (i % STAGES) * STAGE_BYTES;
        uint32_t bb = ab + A_ST;

        #pragma unroll
        for (int ks = 0; ks < 4; ks++) {   // 4 x k32 within the 128B chunk
            uint32_t af[4][4];
            #pragma unroll
            for (int mf = 0; mf < 4; mf++) {
                int row = wm * 64 + mf * 16 + (mi & 1) * 8 + rin;
                int kc = ks * 2 + (mi >> 1);
                ldsm_x4(ab + row * 128 + ((kc ^ (row & 7)) << 4),
                        af[mf][0], af[mf][1], af[mf][2], af[mf][3]);
            }
            uint32_t bfr[2][4];
            #pragma unroll
            for (int nf2 = 0; nf2 < 2; nf2++) {
                int nrow = wn * 32 + (nf2 * 2 + (mi >> 1)) * 8 + rin;
                int kc = ks * 2 + (mi & 1);
                ldsm_x4(bb + nrow * 128 + ((kc ^ (nrow & 7)) << 4),
                        bfr[nf2][0], bfr[nf2][1], bfr[nf2][2], bfr[nf2][3]);
            }
            #pragma unroll
            for (int mf = 0; mf < 4; mf++)
                #pragma unroll
                for (int nf = 0; nf < 4; nf++) {
                    uint32_t b0 = bfr[nf >> 1][(nf & 1) * 2 + 0];
                    uint32_t b1 = bfr[nf >> 1][(nf & 1) * 2 + 1];
                    mma16832s8(acc[mf][nf], af[mf][0], af[mf][1], af[mf][2], af[mf][3],
                               b0, b1);
                }
        }
        // no end-of-iteration barrier (redundant; see comment above)
    }

    // Epilogue: per-row top-2 over this warp's 32 columns (one 32-tile per warp).
    int tileN = blockIdx.x * 4 + wn;
    int colbase = v0 + wn * 32 + (lane & 3) * 2;
    #pragma unroll
    for (int mf = 0; mf < 4; mf++) {
        float bA = -3.4e38f, sA = -3.4e38f, bB = -3.4e38f, sB = -3.4e38f;
        int biA = 0, siA = 0, biB = 0, siB = 0;
        #pragma unroll
        for (int nf = 0; nf < 4; nf++) {
            #pragma unroll
            for (int e = 0; e < 2; e++) {
                int col = colbase + nf * 8 + e;
                top2_merge(bA, sA, biA, siA, (float)acc[mf][nf][e], -3.4e38f, col, 0);
                top2_merge(bB, sB, biB, siB, (float)acc[mf][nf][2 + e], -3.4e38f, col, 0);
            }
        }
        #pragma unroll
        for (int o = 1; o <= 2; o <<= 1) {
            float b2 = __shfl_xor_sync(0xFFFFFFFFu, bA, o);
            float s2 = __shfl_xor_sync(0xFFFFFFFFu, sA, o);
            int bi2 = __shfl_xor_sync(0xFFFFFFFFu, biA, o);
            int si2 = __shfl_xor_sync(0xFFFFFFFFu, siA, o);
            top2_merge(bA, sA, biA, siA, b2, s2, bi2, si2);
            b2 = __shfl_xor_sync(0xFFFFFFFFu, bB, o);
            s2 = __shfl_xor_sync(0xFFFFFFFFu, sB, o);
            bi2 = __shfl_xor_sync(0xFFFFFFFFu, biB, o);
            si2 = __shfl_xor_sync(0xFFFFFFFFu, siB, o);
            top2_merge(bB, sB, biB, siB, b2, s2, bi2, si2);
        }
        if ((lane & 3) == 0) {
            int rowA = m0 + wm * 64 + mf * 16 + (lane >> 2);
            float2* pA = &g_part[((size_t)rowA * NTILE32 + tileN) * 2];
            pA[0] = make_float2(bA, __int_as_float(biA));
            pA[1] = make_float2(sA, __int_as_float(siA));
            float2* pB = &g_part[((size_t)(rowA + 8) * NTILE32 + tileN) * 2];
            pB[0] = make_float2(bB, __int_as_float(biB));
            pB[1] = make_float2(sB, __int_as_float(siB));
        }
    }
}

// ---------------------------------------------------------------------------
// Kernel 4: refine. One warp per row; float4-vectorized exact fp32 dots.
// ---------------------------------------------------------------------------
__global__ void __launch_bounds__(256) k_refine(const float* __restrict__ x,
                                               float* __restrict__ out) {
    int gwarp = (blockIdx.x * blockDim.x + threadIdx.x) >> 5;
    int lid = threadIdx.x & 31;
    if (gwarp >= NROWS) return;
    int row = gwarp;

    const float4* p4 = reinterpret_cast<const float4*>(&g_part[(size_t)row * NTILE32 * 2]);

    // pass 1: max of stored (quantized-domain) best scores
    float mx = -3.4e38f;
    float4 qv[8];
    #pragma unroll
    for (int g = 0; g < 8; g++) {
        qv[g] = p4[g * 32 + lid];          // (best, bi, sec, si)
        mx = fmaxf(mx, qv[g].x);
    }
    #pragma unroll
    for (int o = 16; o; o >>= 1) mx = fmaxf(mx, __shfl_xor_sync(0xFFFFFFFFu, mx, o));
    float thr = mx - MARGIN_I;

    const float4* xr4 = reinterpret_cast<const float4*>(x + (size_t)row * DDIM);
    float bestv = -3.4e38f;
    int besti = 0x7FFFFFFF;

    // pass 2: exact fp32 dot for every candidate above threshold (best + sec)
    #pragma unroll
    for (int g = 0; g < 8; g++) {
        #pragma unroll
        for (int h = 0; h < 2; h++) {
            float sc = h ? qv[g].z : qv[g].x;
            int myidx = __float_as_int(h ? qv[g].w : qv[g].y);
            unsigned mask = __ballot_sync(0xFFFFFFFFu, sc >= thr);
            while (mask) {
                int s = __ffs(mask) - 1;
                mask &= mask - 1;
                int idx = __shfl_sync(0xFFFFFFFFu, myidx, s);
                const float4* dr4 = reinterpret_cast<const float4*>(
                    g_dTf + (size_t)idx * DDIM);
                float a = 0.0f;
                #pragma unroll 4
                for (int k = lid; k < DDIM / 4; k += 32) {
                    float4 xv = xr4[k], dv = dr4[k];
                    a = fmaf(xv.x, dv.x, a);
                    a = fmaf(xv.y, dv.y, a);
                    a = fmaf(xv.z, dv.z, a);
                    a = fmaf(xv.w, dv.w, a);
                }
                #pragma unroll
                for (int o = 16; o; o >>= 1) a += __shfl_xor_sync(0xFFFFFFFFu, a, o);
                if (a > bestv || (a == bestv && idx < besti)) { bestv = a; besti = idx; }
            }
        }
    }
    if (lid == 0) out[row] = (float)besti;
}

// ---------------------------------------------------------------------------
// Launch
// ---------------------------------------------------------------------------
extern "C" void kernel_launch(void* const* d_in, const int* in_sizes, int n_in,
                              void* d_out, int out_size) {
    const float* x = (const float*)d_in[0];
    const float* di = (const float*)d_in[1];
    float* out = (float*)d_out;

    cudaFuncSetAttribute(k_gemm, cudaFuncAttributeMaxDynamicSharedMemorySize, GEMM_SMEM);

    k_convert_x<<<2048, 256>>>(x);

    dim3 tg(VDIM / 32, DDIM / 32);
    k_transpose_di<<<tg, dim3(32, 8)>>>(di);

    dim3 gg(VDIM / BN, NROWS / BM);  // 64 x 128 = 8192 CTAs
    k_gemm<<<gg, 256, GEMM_SMEM>>>();

    k_refine<<<NROWS / 8, 256>>>(x, out);
}